// round 10
// baseline (speedup 1.0000x reference)
#include <cuda_runtime.h>
#include <cuda_bf16.h>

typedef unsigned int u32;

#define DIM 64
#define NHID 256
#define W0_SZ (DIM*NHID)
#define W1_SZ (NHID*NHID)
#define W2_SZ (NHID*DIM)
#define WNET  (W0_SZ+W1_SZ+W2_SZ)

#define TBR 64
#define NTHREADS 256

// fragment-packed weight stream, per wn-group:
// per pair: stage0 4 chunks x (hi2048+lo2048) + stage1 16 x 4096 + stage2 16 x (hi512+lo512)
#define GRP_PAIR 98304
#define GRP_STRIDE ((size_t)32*GRP_PAIR)    /* 3145728 */

#define SM_AHI 0u          /* 64 x 512B swizzled bf16 tile */
#define SM_ALO 32768u
#define SM_LOC 65536u      /* 64 x 66 fp32 */
#define SM_Y   82432u      /* 64 x 66 fp32 */
#define SM_TOTAL 99328u

// +16KB pad: register/L1 prefetch may read up to two items past the stream end
__device__ __align__(16) unsigned char g_W[(size_t)4*GRP_STRIDE + 16384];

static __device__ __forceinline__ u32 s2u(const void* p){
  u32 a; asm("{ .reg .u64 t; cvta.to.shared.u64 t, %1; cvt.u32.u64 %0, t; }":"=r"(a):"l"(p)); return a;
}
static __device__ __forceinline__ void ldsm4(u32* r, u32 a){
  asm volatile("ldmatrix.sync.aligned.m8n8.x4.shared.b16 {%0,%1,%2,%3}, [%4];"
    :"=r"(r[0]),"=r"(r[1]),"=r"(r[2]),"=r"(r[3]):"r"(a));
}
static __device__ __forceinline__ void mma_bf16(float* d, const u32* a, const u32* b){
  asm volatile("mma.sync.aligned.m16n8k16.row.col.f32.bf16.bf16.f32 "
    "{%0,%1,%2,%3}, {%4,%5,%6,%7}, {%8,%9}, {%0,%1,%2,%3};"
    :"+f"(d[0]),"+f"(d[1]),"+f"(d[2]),"+f"(d[3])
    :"r"(a[0]),"r"(a[1]),"r"(a[2]),"r"(a[3]),"r"(b[0]),"r"(b[1]));
}
static __device__ __forceinline__ void pfl1(const void* p){
  asm volatile("prefetch.global.L1 [%0];"::"l"(p));
}
static __device__ __forceinline__ u32 packbf(float lo, float hi){
  u32 r; asm("cvt.rn.bf16x2.f32 %0, %1, %2;":"=r"(r):"f"(hi),"f"(lo)); return r;
}
// write 2 consecutive cols (c,c+1) of one row into A hi/lo swizzled tiles
static __device__ __forceinline__ void writeA2(unsigned char* smp, int row, int c, float v0, float v1){
  u32 unit = (u32)c >> 3;
  u32 off = (u32)row*512u + (((unit ^ ((u32)row & 7u)) << 4) | (((u32)c & 7u) << 1));
  u32 h = packbf(v0, v1);
  float h0 = __uint_as_float(h << 16);
  float h1 = __uint_as_float(h & 0xFFFF0000u);
  u32 lo = packbf(v0 - h0, v1 - h1);
  *(u32*)(smp + SM_AHI + off) = h;
  *(u32*)(smp + SM_ALO + off) = lo;
}

// ---------- prep: mask, bf16 hi/lo split, mma-fragment-order image -----------
__global__ void prep_kernel(
    const float* __restrict__ lW0, const float* __restrict__ lW1, const float* __restrict__ lW2,
    const float* __restrict__ sW0, const float* __restrict__ sW1, const float* __restrict__ sW2,
    const float* __restrict__ M0,  const float* __restrict__ M1,  const float* __restrict__ M2)
{
    int idx = blockIdx.x*blockDim.x + threadIdx.x;
    if (idx >= 32*WNET) return;
    int pair = idx / WNET, off = idx % WNET;
    int l = pair >> 1, net = pair & 1;
    float w; int n, k, wn, nl, itemoff, lodelta;
    if (off < W0_SZ){
        n = off >> 6; k = off & 63;
        int s = l*W0_SZ + off;
        w = (net ? sW0[s] : lW0[s]) * M0[s];
        wn = n >> 6; nl = n & 63;
        itemoff = (k >> 4)*4096; lodelta = 2048;
    } else if (off < W0_SZ + W1_SZ){
        int o = off - W0_SZ;
        n = o >> 8; k = o & 255;
        int s = l*W1_SZ + o;
        w = (net ? sW1[s] : lW1[s]) * M1[s];
        wn = n >> 6; nl = n & 63;
        itemoff = 16384 + (k >> 4)*4096; lodelta = 2048;
    } else {
        int o = off - W0_SZ - W1_SZ;
        n = o >> 8; k = o & 255;
        int s = l*W2_SZ + o;
        w = (net ? sW2[s] : lW2[s]) * M2[s];
        wn = n >> 4; nl = n & 15;
        itemoff = 81920 + (k >> 4)*1024; lodelta = 512;
    }
    int g = nl >> 4, nn = nl & 15, tt = nn >> 3, nrow = nn & 7, kl = k & 15;
    int T = (nrow << 2) | ((kl & 7) >> 1);
    int b = (tt << 1) | (kl >> 3);
    size_t dst = (size_t)wn*GRP_STRIDE + (size_t)pair*GRP_PAIR
               + itemoff + g*512 + T*16 + b*4 + ((kl & 1) << 1);
    __nv_bfloat16 hv = __float2bfloat16_rn(w);
    __nv_bfloat16 lv = __float2bfloat16_rn(w - __bfloat162float(hv));
    *(__nv_bfloat16*)(g_W + dst) = hv;
    *(__nv_bfloat16*)(g_W + dst + lodelta) = lv;
}

// ---------------- fused flow kernel ------------------------------------------
__global__ void __launch_bounds__(NTHREADS,2) flow_kernel(
    const float* __restrict__ u,
    const float* __restrict__ lb0, const float* __restrict__ lb1, const float* __restrict__ lb2,
    const float* __restrict__ sb0, const float* __restrict__ sb1, const float* __restrict__ sb2,
    float* __restrict__ out)
{
    extern __shared__ unsigned char smp[];
    u32 smb = s2u(smp);
    int tid = threadIdx.x, lane = tid & 31, wid = tid >> 5;
    int wm = wid >> 2, wn = wid & 3;
    int q = lane >> 3, ln = lane & 7;
    int row0 = blockIdx.x * TBR;
    float* loc_sm = (float*)(smp + SM_LOC);
    float* y_sm   = (float*)(smp + SM_Y);

    int r0  = wm*32 + (lane >> 2);
    int cb  = wn*64 + (lane & 3)*2;   // stage0/1 col base (N=256)
    int cb2 = wn*16 + (lane & 3)*2;   // stage2 col base (N=64)

    // per-thread weight stream base (fragment order: this lane's 16B slices)
    const unsigned char* tb = g_W + (size_t)wn*GRP_STRIDE + (size_t)lane*16;

    // init y smem + A tiles (cols 0..63)
    #pragma unroll
    for (int i = 0; i < 2; i++)
      #pragma unroll
      for (int j = 0; j < 2; j++)
        #pragma unroll
        for (int rr = 0; rr < 2; rr++){
          int row = r0 + i*16 + rr*8;
          int c = cb2 + j*8;
          float2 v = *(const float2*)(u + (size_t)(row0 + row)*DIM + c);
          *(float2*)&y_sm[row*66 + c] = v;
          writeA2(smp, row, c, v.x, v.y);
        }
    __syncthreads();

    float acc[16][4];
    uint4 bh[4];
    auto zacc = [&](){
        #pragma unroll
        for (int t = 0; t < 16; t++){ acc[t][0]=0.f; acc[t][1]=0.f; acc[t][2]=0.f; acc[t][3]=0.f; }
    };
    auto ldA = [&](u32 base, int kc, u32 (*r)[4]){
        u32 arow0 = (u32)(wm*32 + ((q & 1) << 3) + ln);
        u32 aunit = (u32)(kc*2 + (q >> 1));
        #pragma unroll
        for (int i = 0; i < 2; i++){
            u32 rr = arow0 + (u32)i*16u;
            u32 aoff = rr*512u + ((aunit ^ (rr & 7u)) << 4);
            ldsm4(r[i], base + aoff);
        }
    };
    // big chunk: bh preloaded; reg-prefetch of next bh between pass2/pass3;
    // L1 prefetch of item-after-next. Per-acc order: ah*bh, al*bh, ah*bl.
    auto big_chunk = [&](const unsigned char* wp_cur, int kc){
        u32 ah[2][4], al[2][4];
        ldA(smb + SM_AHI, kc, ah);
        uint4 bl[4];
        #pragma unroll
        for (int g = 0; g < 4; g++) bl[g] = *(const uint4*)(wp_cur + 2048 + g*512);
        ldA(smb + SM_ALO, kc, al);
        // pass1: ah * bh
        #pragma unroll
        for (int g = 0; g < 4; g++){
            const u32* bp = (const u32*)&bh[g];
            #pragma unroll
            for (int i = 0; i < 2; i++)
              #pragma unroll
              for (int tt = 0; tt < 2; tt++)
                mma_bf16(acc[i*8 + g*2 + tt], ah[i], bp + tt*2);
        }
        // warm L1 for the bh half of the item after next
        #pragma unroll
        for (int g = 0; g < 4; g++) pfl1(wp_cur + 8192 + g*512);
        // pass2: al * bh
        #pragma unroll
        for (int g = 0; g < 4; g++){
            const u32* bp = (const u32*)&bh[g];
            #pragma unroll
            for (int i = 0; i < 2; i++)
              #pragma unroll
              for (int tt = 0; tt < 2; tt++)
                mma_bf16(acc[i*8 + g*2 + tt], al[i], bp + tt*2);
        }
        // register-prefetch next item's bh (L1-warm from previous chunk's pfl1)
        #pragma unroll
        for (int g = 0; g < 4; g++) bh[g] = *(const uint4*)(wp_cur + 4096 + g*512);
        // warm L1 for the bl half of the item after next
        #pragma unroll
        for (int g = 0; g < 4; g++) pfl1(wp_cur + 8192 + 2048 + g*512);
        // pass3: ah * bl
        #pragma unroll
        for (int g = 0; g < 4; g++){
            const u32* bp = (const u32*)&bl[g];
            #pragma unroll
            for (int i = 0; i < 2; i++)
              #pragma unroll
              for (int tt = 0; tt < 2; tt++)
                mma_bf16(acc[i*8 + g*2 + tt], ah[i], bp + tt*2);
        }
    };
    // small chunk (stage2): bh[0] preloaded; same prefetch discipline
    auto small_chunk = [&](const unsigned char* wp_cur, int kc){
        u32 ah[2][4], al[2][4];
        ldA(smb + SM_AHI, kc, ah);
        uint4 bl = *(const uint4*)(wp_cur + 512);
        ldA(smb + SM_ALO, kc, al);
        const u32* bhp = (const u32*)&bh[0];
        const u32* blp = (const u32*)&bl;
        #pragma unroll
        for (int i = 0; i < 2; i++)
          #pragma unroll
          for (int tt = 0; tt < 2; tt++)
            mma_bf16(acc[i*8 + tt], ah[i], bhp + tt*2);
        pfl1(wp_cur + 2048);
        #pragma unroll
        for (int i = 0; i < 2; i++)
          #pragma unroll
          for (int tt = 0; tt < 2; tt++)
            mma_bf16(acc[i*8 + tt], al[i], bhp + tt*2);
        bh[0] = *(const uint4*)(wp_cur + 1024);
        pfl1(wp_cur + 2048 + 512);
        #pragma unroll
        for (int i = 0; i < 2; i++)
          #pragma unroll
          for (int tt = 0; tt < 2; tt++)
            mma_bf16(acc[i*8 + tt], ah[i], blp + tt*2);
    };

    #pragma unroll 1
    for (int pair = 0; pair < 32; pair++){
        int l = pair >> 1, net = pair & 1;
        const float* b0 = (net ? sb0 : lb0) + l*NHID;
        const float* b1 = (net ? sb1 : lb1) + l*NHID;
        const float* b2 = (net ? sb2 : lb2) + l*DIM;
        const unsigned char* wp0 = tb + (size_t)pair*GRP_PAIR;

        // preload bh for stage0 chunk0
        #pragma unroll
        for (int g = 0; g < 4; g++) bh[g] = *(const uint4*)(wp0 + g*512);

        // ---- stage0: K=64 ----
        zacc();
        #pragma unroll 1
        for (int kc = 0; kc < 4; kc++) big_chunk(wp0 + kc*4096, kc);
        __syncthreads();
        #pragma unroll
        for (int i = 0; i < 2; i++)
          #pragma unroll
          for (int j = 0; j < 8; j++){
            int c = cb + j*8;
            float2 bb = *(const float2*)(b0 + c);
            float* d = acc[i*8 + j];
            writeA2(smp, r0 + i*16,     c, fmaxf(d[0]+bb.x,0.f), fmaxf(d[1]+bb.y,0.f));
            writeA2(smp, r0 + i*16 + 8, c, fmaxf(d[2]+bb.x,0.f), fmaxf(d[3]+bb.y,0.f));
          }
        __syncthreads();

        // ---- stage1: K=256 ---- (bh already prefetched by stage0's last chunk)
        zacc();
        #pragma unroll 1
        for (int kc = 0; kc < 16; kc++) big_chunk(wp0 + 16384 + kc*4096, kc);
        __syncthreads();
        #pragma unroll
        for (int i = 0; i < 2; i++)
          #pragma unroll
          for (int j = 0; j < 8; j++){
            int c = cb + j*8;
            float2 bb = *(const float2*)(b1 + c);
            float* d = acc[i*8 + j];
            writeA2(smp, r0 + i*16,     c, fmaxf(d[0]+bb.x,0.f), fmaxf(d[1]+bb.y,0.f));
            writeA2(smp, r0 + i*16 + 8, c, fmaxf(d[2]+bb.x,0.f), fmaxf(d[3]+bb.y,0.f));
          }
        __syncthreads();

        // ---- stage2: K=256, N=64 ----
        zacc();
        bh[0] = *(const uint4*)(wp0 + 81920);
        #pragma unroll 1
        for (int kc = 0; kc < 16; kc++) small_chunk(wp0 + 81920 + kc*1024, kc);
        __syncthreads();
        if (net == 0){
            #pragma unroll
            for (int i = 0; i < 2; i++)
              #pragma unroll
              for (int j = 0; j < 2; j++){
                int c = cb2 + j*8;
                float2 bb = *(const float2*)(b2 + c);
                float* d = acc[i*8 + j];
                int ra = r0 + i*16, rb = ra + 8;
                *(float2*)&loc_sm[ra*66 + c] = make_float2(d[0]+bb.x, d[1]+bb.y);
                *(float2*)&loc_sm[rb*66 + c] = make_float2(d[2]+bb.x, d[3]+bb.y);
                float2 ya = *(const float2*)&y_sm[ra*66 + c];
                float2 yb = *(const float2*)&y_sm[rb*66 + c];
                writeA2(smp, ra, c, ya.x, ya.y);
                writeA2(smp, rb, c, yb.x, yb.y);
              }
        } else {
            #pragma unroll
            for (int i = 0; i < 2; i++)
              #pragma unroll
              for (int j = 0; j < 2; j++){
                int c = cb2 + j*8;
                float2 bb = *(const float2*)(b2 + c);
                float* d = acc[i*8 + j];
                #pragma unroll
                for (int rr = 0; rr < 2; rr++){
                  int row = r0 + i*16 + rr*8;
                  float2 lc = *(const float2*)&loc_sm[row*66 + c];
                  float2 yo = *(const float2*)&y_sm[row*66 + c];
                  float y0 = expf(-(d[rr*2]  + bb.x)) * (yo.x - lc.x);
                  float y1 = expf(-(d[rr*2+1]+ bb.y)) * (yo.y - lc.y);
                  if (pair == 31){
                    *(float2*)(out + (size_t)(row0 + row)*DIM + c) = make_float2(y0, y1);
                  } else {
                    *(float2*)&y_sm[row*66 + c] = make_float2(y0, y1);
                    writeA2(smp, row, c, y0, y1);
                  }
                }
              }
        }
        __syncthreads();
    }
}

// ---------------- launch ------------------------------------------------------
extern "C" void kernel_launch(void* const* d_in, const int* in_sizes, int n_in,
                              void* d_out, int out_size)
{
    const float* u   = (const float*)d_in[0];
    const float* lW0 = (const float*)d_in[1];
    const float* lb0 = (const float*)d_in[2];
    const float* lW1 = (const float*)d_in[3];
    const float* lb1 = (const float*)d_in[4];
    const float* lW2 = (const float*)d_in[5];
    const float* lb2 = (const float*)d_in[6];
    const float* sW0 = (const float*)d_in[7];
    const float* sb0 = (const float*)d_in[8];
    const float* sW1 = (const float*)d_in[9];
    const float* sb1 = (const float*)d_in[10];
    const float* sW2 = (const float*)d_in[11];
    const float* sb2 = (const float*)d_in[12];
    const float* M0  = (const float*)d_in[13];
    const float* M1  = (const float*)d_in[14];
    const float* M2  = (const float*)d_in[15];

    int rows = in_sizes[0] / DIM;

    cudaFuncSetAttribute(flow_kernel, cudaFuncAttributeMaxDynamicSharedMemorySize, SM_TOTAL);

    const int total = 32*WNET;
    prep_kernel<<<(total + 255)/256, 256>>>(lW0, lW1, lW2, sW0, sW1, sW2, M0, M1, M2);

    flow_kernel<<<rows / TBR, NTHREADS, SM_TOTAL>>>(
        u, lb0, lb1, lb2, sb0, sb1, sb2, (float*)d_out);
}